// round 7
// baseline (speedup 1.0000x reference)
#include <cuda_runtime.h>
#include <math.h>

#define FULL 0xFFFFFFFFu

constexpr int B  = 64;
constexpr int P  = 4096;
constexpr int W  = 16;
constexpr int D  = 128;
constexpr int Dw = 64;

// W1r: (D, D+4) row-major, stride 132.  W1t: (D, 2*Dw+2) row-major, stride 130.

__device__ float g_src[W * D];    // wh_emb @ W1t_src.T + b1t
__device__ float g_tgt[W * D];    // wh_emb @ W1t_tgt.T
__device__ float g_emb[P * D];    // part_emb @ W1r_e.T + b1r + 0.95*W1r[:,130]

// ---------------------------------------------------------------------------
// 4-way batched warp reduction (6 shuffles for 4 sums).
// lane group j = ((lane>>4)&1) | ((lane>>2)&2) holds total of s_j.
// ---------------------------------------------------------------------------
__device__ __forceinline__ float fold4(float s0, float s1, float s2, float s3) {
    bool hi16 = (threadIdx.x & 16) != 0;
    bool hi8  = (threadIdx.x & 8) != 0;
    float a   = hi16 ? s0 : s1;
    float v01 = (hi16 ? s1 : s0) + __shfl_xor_sync(FULL, a, 16);
    float b   = hi16 ? s2 : s3;
    float v23 = (hi16 ? s3 : s2) + __shfl_xor_sync(FULL, b, 16);
    float c   = hi8 ? v01 : v23;
    float vv  = (hi8 ? v23 : v01) + __shfl_xor_sync(FULL, c, 8);
    vv += __shfl_xor_sync(FULL, vv, 4);
    vv += __shfl_xor_sync(FULL, vv, 2);
    vv += __shfl_xor_sync(FULL, vv, 1);
    return vv;
}

// ---------------------------------------------------------------------------
// k_head (launch 1, 144 blocks x 256 thr, dyn smem 68096B):
//   blocks [0,128): emb (32 p each), blocks [128,144): src/tgt mini-GEMMs
// ---------------------------------------------------------------------------
__global__ void k_head(const float* __restrict__ part_emb,
                       const float* __restrict__ wh_emb,
                       const float* __restrict__ W1r,
                       const float* __restrict__ b1r,
                       const float* __restrict__ W1t,
                       const float* __restrict__ b1t) {
    extern __shared__ float dsm[];          // sWT[128*132] + sBias[128]
    int bid = blockIdx.x, tid = threadIdx.x;

    if (bid >= 128) {
        int idx = (bid - 128) * 256 + tid;  // 0..4095
        int arr = idx >> 11;
        int rem = idx & 2047;
        int s = rem >> 7, d = rem & 127;
        const float* wrow = wh_emb + s * Dw;
        const float* wcol = W1t + d * 130 + arr * Dw;
        float acc = (arr == 0) ? b1t[d] : 0.f;
        #pragma unroll 8
        for (int k = 0; k < Dw; k++) acc = fmaf(wrow[k], wcol[k], acc);
        if (arr == 0) g_src[s * D + d] = acc;
        else          g_tgt[s * D + d] = acc;
        return;
    }

    float* sWT   = dsm;                     // [k*132 + d]
    float* sBias = dsm + 128 * 132;
    for (int i = tid; i < 128 * 128; i += 256) {
        int d = i >> 7, k = i & 127;
        sWT[k * 132 + d] = W1r[d * 132 + k];
    }
    if (tid < 128) sBias[tid] = b1r[tid] + 0.95f * W1r[tid * 132 + 130];
    __syncthreads();

    int w = tid >> 5, lane = tid & 31;
    int p0 = bid * 32 + w * 4;
    const float4* e0 = (const float4*)(part_emb + (p0 + 0) * D);
    const float4* e1 = (const float4*)(part_emb + (p0 + 1) * D);
    const float4* e2 = (const float4*)(part_emb + (p0 + 2) * D);
    const float4* e3 = (const float4*)(part_emb + (p0 + 3) * D);
    float4 bias = ((const float4*)sBias)[lane];
    float4 a0 = bias, a1 = bias, a2 = bias, a3 = bias;
    #pragma unroll 4
    for (int k4 = 0; k4 < 32; k4++) {
        const float* wt = sWT + k4 * 4 * 132;
        float4 w0 = ((const float4*)(wt))[lane];
        float4 w1 = ((const float4*)(wt + 132))[lane];
        float4 w2 = ((const float4*)(wt + 264))[lane];
        float4 w3 = ((const float4*)(wt + 396))[lane];
        float4 ea = __ldg(&e0[k4]);
        float4 eb = __ldg(&e1[k4]);
        float4 ec = __ldg(&e2[k4]);
        float4 ed = __ldg(&e3[k4]);
        #define ACC(A, E) \
            A.x = fmaf(E.x, w0.x, fmaf(E.y, w1.x, fmaf(E.z, w2.x, fmaf(E.w, w3.x, A.x)))); \
            A.y = fmaf(E.x, w0.y, fmaf(E.y, w1.y, fmaf(E.z, w2.y, fmaf(E.w, w3.y, A.y)))); \
            A.z = fmaf(E.x, w0.z, fmaf(E.y, w1.z, fmaf(E.z, w2.z, fmaf(E.w, w3.z, A.z)))); \
            A.w = fmaf(E.x, w0.w, fmaf(E.y, w1.w, fmaf(E.z, w2.w, fmaf(E.w, w3.w, A.w))));
        ACC(a0, ea) ACC(a1, eb) ACC(a2, ec) ACC(a3, ed)
        #undef ACC
    }
    ((float4*)(g_emb + (p0 + 0) * D))[lane] = a0;
    ((float4*)(g_emb + (p0 + 1) * D))[lane] = a1;
    ((float4*)(g_emb + (p0 + 2) * D))[lane] = a2;
    ((float4*)(g_emb + (p0 + 3) * D))[lane] = a3;
}

// ---------------------------------------------------------------------------
// k_main (launch 2, 1536 blocks x 256 thr):
//   blocks [0,1024): transfer, 4 p each (8 warps = 4 p x 2 parity)
//   blocks [1024,1536): reorder, 8 p each (warp per p)
// ---------------------------------------------------------------------------
__global__ void __launch_bounds__(256, 5)
k_main(const float* __restrict__ cur_stock,
       const float* __restrict__ demand,
       const float* __restrict__ lead,
       const float* __restrict__ wstk,
       const float* __restrict__ wdem,
       const float* __restrict__ W1r,
       const float* __restrict__ W2r,
       const float* __restrict__ b2r,
       const float* __restrict__ W1t,
       const float* __restrict__ W2t,
       const float* __restrict__ b2t,
       float* __restrict__ outR,
       float* __restrict__ outT) {
    __shared__ union {
        struct {
            float sSrc[W * D];
            float sTgt[W * D];
            float sWs[D], sWd[D], sV[D];
            float sRes[256 * 5];    // raw scores [s*16+t][4 p + pad]
            float sSv[4 * 17];
            int   sPl[4 * 17];
            int   sTl[4 * 17];
        } t;
        struct {
            float sC[4 * 128];
            float sX[8][65];
        } r;
    } sm;

    int tid = threadIdx.x;
    int bid = blockIdx.x;
    int w = tid >> 5, lane = tid & 31;
    int jm = ((lane >> 4) & 1) | ((lane >> 2) & 2);

    if (bid >= 1024) {
        // ================= reorder role: 8 p, warp per p =================
        if (tid < 128) {
            sm.r.sC[tid]       = W1r[tid * 132 + 128];
            sm.r.sC[128 + tid] = W1r[tid * 132 + 129];
            // note: column 131 is current_stock coeff, 130 folded into emb
            sm.r.sC[256 + tid] = W1r[tid * 132 + 131];
            sm.r.sC[384 + tid] = W2r[tid];
        }
        __syncthreads();

        float4 c0 = ((float4*)sm.r.sC)[lane];
        float4 c1 = ((float4*)(sm.r.sC + 128))[lane];
        float4 c3 = ((float4*)(sm.r.sC + 256))[lane];
        float4 v  = ((float4*)(sm.r.sC + 384))[lane];

        int pbase = (bid - 1024) * 8;
        int p = pbase + w;
        float4 e = ((const float4*)(g_emb + p * D))[lane];

        #pragma unroll 2
        for (int bq = 0; bq < B; bq += 8) {
            float sA[8];
            #pragma unroll
            for (int j = 0; j < 8; j++) {
                int item = (bq + j) * P + p;
                float df = __ldg(&demand[item]);
                float lt = __ldg(&lead[item]);
                float cs = __ldg(&cur_stock[item]);
                float4 h;
                h.x = fmaxf(fmaf(cs, c3.x, fmaf(lt, c1.x, fmaf(df, c0.x, e.x))), 0.f);
                h.y = fmaxf(fmaf(cs, c3.y, fmaf(lt, c1.y, fmaf(df, c0.y, e.y))), 0.f);
                h.z = fmaxf(fmaf(cs, c3.z, fmaf(lt, c1.z, fmaf(df, c0.z, e.z))), 0.f);
                h.w = fmaxf(fmaf(cs, c3.w, fmaf(lt, c1.w, fmaf(df, c0.w, e.w))), 0.f);
                sA[j] = fmaf(h.x, v.x, fmaf(h.y, v.y, fmaf(h.z, v.z, h.w * v.w)));
            }
            // two independent reduction chains overlap
            float t0 = fold4(sA[0], sA[1], sA[2], sA[3]);
            float t1 = fold4(sA[4], sA[5], sA[6], sA[7]);
            if ((lane & 7) == 0) {
                sm.r.sX[w][bq + jm]     = t0;
                sm.r.sX[w][bq + 4 + jm] = t1;
            }
        }
        __syncthreads();

        float bb = b2r[0];
        for (int i = tid; i < 512; i += 256) {
            int b = i >> 3, pw = i & 7;
            float x = sm.r.sX[pw][b] + bb;
            outR[b * P + pbase + pw] = fmaxf(x, 0.f) + log1pf(__expf(-fabsf(x)));
        }
        return;
    }

    // ================= transfer role: 4 p x 2 parity warps =================
    {
        const float4* gs = (const float4*)g_src;
        const float4* gt = (const float4*)g_tgt;
        float4* ss = (float4*)sm.t.sSrc;
        float4* st4 = (float4*)sm.t.sTgt;
        for (int i = tid; i < W * D / 4; i += 256) { ss[i] = gs[i]; st4[i] = gt[i]; }
    }
    if (tid < D) {
        sm.t.sWs[tid] = W1t[tid * 130 + 128];
        sm.t.sWd[tid] = W1t[tid * 130 + 129];
        sm.t.sV[tid]  = W2t[tid];
    }

    int pslot = w >> 1;                 // 0..3
    int q = w & 1;
    int pbase = bid * 4;
    int p = pbase + pslot;

    float sv = 0.f;
    if (lane < W) sv = wstk[lane * P + p] - wdem[lane * P + p];
    unsigned pos = __ballot_sync(FULL, (lane < W) && (sv > 0.f));
    unsigned neg = __ballot_sync(FULL, (lane < W) && (sv < 0.f));
    int npos = __popc(pos);
    int nneg = __popc(neg);

    if (q == 0 && lane < W) {
        sm.t.sSv[pslot * 17 + lane] = sv;
        unsigned bit = 1u << lane;
        if (pos & bit) sm.t.sPl[pslot * 17 + __popc(pos & (bit - 1))] = lane;
        if (neg & bit) sm.t.sTl[pslot * 17 + __popc(neg & (bit - 1))] = lane;
    }
    __syncthreads();

    float4 ws4 = ((float4*)sm.t.sWs)[lane];
    float4 wd4 = ((float4*)sm.t.sWd)[lane];
    float4 v4  = ((float4*)sm.t.sV)[lane];

    const float* svRow = sm.t.sSv + pslot * 17;
    const int*   tl    = sm.t.sTl + pslot * 17;

    for (int si = q; si < npos; si += 2) {
        int s = sm.t.sPl[pslot * 17 + si];
        float ssp = svRow[s];
        float4 sr = ((float4*)(sm.t.sSrc + s * D))[lane];
        float4 base;
        base.x = fmaf(ssp, ws4.x, sr.x);
        base.y = fmaf(ssp, ws4.y, sr.y);
        base.z = fmaf(ssp, ws4.z, sr.z);
        base.w = fmaf(ssp, ws4.w, sr.w);
        for (int ti = 0; ti < nneg; ti += 8) {
            float sA[8];
            int tt[8];
            #pragma unroll
            for (int j = 0; j < 8; j++) {
                int idx = ti + j; if (idx > nneg - 1) idx = nneg - 1;
                int t = tl[idx];
                tt[j] = t;
                float dn = -svRow[t];
                float4 tg = ((float4*)(sm.t.sTgt + t * D))[lane];
                float4 h;
                h.x = fmaxf(base.x + fmaf(dn, wd4.x, tg.x), 0.f);
                h.y = fmaxf(base.y + fmaf(dn, wd4.y, tg.y), 0.f);
                h.z = fmaxf(base.z + fmaf(dn, wd4.z, tg.z), 0.f);
                h.w = fmaxf(base.w + fmaf(dn, wd4.w, tg.w), 0.f);
                sA[j] = fmaf(h.x, v4.x, fmaf(h.y, v4.y, fmaf(h.z, v4.z, h.w * v4.w)));
            }
            float tot0 = fold4(sA[0], sA[1], sA[2], sA[3]);
            float tot1 = fold4(sA[4], sA[5], sA[6], sA[7]);
            int tm0 = (lane & 16) ? ((lane & 8) ? tt[3] : tt[1])
                                  : ((lane & 8) ? tt[2] : tt[0]);
            int tm1 = (lane & 16) ? ((lane & 8) ? tt[7] : tt[5])
                                  : ((lane & 8) ? tt[6] : tt[4]);
            if (((lane & 7) == 0) && (ti + jm < nneg))
                sm.t.sRes[(s * 16 + tm0) * 5 + pslot] = tot0;
            if (((lane & 7) == 0) && (ti + 4 + jm < nneg))
                sm.t.sRes[(s * 16 + tm1) * 5 + pslot] = tot1;
        }
    }
    __syncthreads();

    float b2 = b2t[0];
    for (int i = tid; i < 1024; i += 256) {
        int st = i >> 2, pw = i & 3;
        int s = st >> 4, t = st & 15;
        float svs = sm.t.sSv[pw * 17 + s];
        float svt = sm.t.sSv[pw * 17 + t];
        float val = 0.f;
        if (svs > 0.f && svt < 0.f) {
            float x = sm.t.sRes[st * 5 + pw] + b2;
            val = fminf(svs, -svt) * __fdividef(1.f, 1.f + __expf(-x));
        }
        outT[st * P + pbase + pw] = val;
    }
}

// ---------------------------------------------------------------------------
extern "C" void kernel_launch(void* const* d_in, const int* in_sizes, int n_in,
                              void* d_out, int out_size) {
    const float* current_stock     = (const float*)d_in[0];
    const float* demand_forecast   = (const float*)d_in[1];
    const float* lead_times        = (const float*)d_in[2];
    const float* warehouse_stocks  = (const float*)d_in[3];
    const float* warehouse_demands = (const float*)d_in[4];
    const float* part_emb          = (const float*)d_in[5];
    const float* wh_emb            = (const float*)d_in[6];
    const float* W1r               = (const float*)d_in[7];
    const float* b1r               = (const float*)d_in[8];
    const float* W2r               = (const float*)d_in[9];
    const float* b2r               = (const float*)d_in[10];
    const float* W1t               = (const float*)d_in[11];
    const float* b1t               = (const float*)d_in[12];
    const float* W2t               = (const float*)d_in[13];
    const float* b2t               = (const float*)d_in[14];

    float* out_reorder  = (float*)d_out;              // [B, P]
    float* out_transfer = (float*)d_out + B * P;      // [W, W, P]

    const int dyn = (128 * 132 + 128) * sizeof(float);   // 68096 B
    static bool attr_set = false;
    if (!attr_set) {
        cudaFuncSetAttribute(k_head, cudaFuncAttributeMaxDynamicSharedMemorySize, dyn);
        attr_set = true;
    }

    k_head<<<144, 256, dyn>>>(part_emb, wh_emb, W1r, b1r, W1t, b1t);
    k_main<<<1536, 256>>>(current_stock, demand_forecast, lead_times,
                          warehouse_stocks, warehouse_demands,
                          W1r, W2r, b2r, W1t, W2t, b2t,
                          out_reorder, out_transfer);
}